// round 6
// baseline (speedup 1.0000x reference)
#include <cuda_runtime.h>
#include <cstdint>
#include <cstddef>

// GRU: T=1024, B=64, I=512, H=512
#define Tn 1024
#define Bn 64
#define In 512
#define Hn 512
#define JB 4          // hidden units per block (scan)
#define HPAD 516      // padded h row: lane stride 516 mod 32 = 4 -> conflict-free phases
#define NBLK 128      // scan blocks (<= #SMs, all co-resident)

typedef unsigned long long ull;

// ---------------- device scratch (no allocations allowed) ----------------
__device__ float g_gi[(size_t)Tn * 1536 * Bn];   // [t][row(1536)][b]  ~402 MB
__device__ float g_h[2][Bn * Hn];                // ping-pong hidden state
__device__ unsigned g_flag[NBLK];                // per-block epoch flags (monotonic)

// ---------------- packed fp32x2 helpers (bit-exact 2x FFMA) ----------------
__device__ __forceinline__ void fma2(ull& d, ull a, ull b) {
    asm("fma.rn.f32x2 %0, %1, %2, %0;" : "+l"(d) : "l"(a), "l"(b));
}
__device__ __forceinline__ float hsum2(ull v) {
    float x, y;
    asm("mov.b64 {%0, %1}, %2;" : "=f"(x), "=f"(y) : "l"(v));
    return x + y;
}
__device__ __forceinline__ unsigned ld_acquire_gpu(const unsigned* p) {
    unsigned v;
    asm volatile("ld.acquire.gpu.global.u32 %0, [%1];" : "=r"(v) : "l"(p) : "memory");
    return v;
}
__device__ __forceinline__ void st_release_gpu(unsigned* p, unsigned v) {
    asm volatile("st.release.gpu.global.u32 [%0], %1;" :: "l"(p), "r"(v) : "memory");
}

// =====================================================================
// Phase 1: GI[t][row][b] = sum_k X[t][b][k] * Wih[row][k] + bih[row]
// =====================================================================
__global__ __launch_bounds__(256, 2) void gemm_ih_kernel(
    const float* __restrict__ X, const float* __restrict__ Wih,
    const float* __restrict__ bih)
{
    __shared__ float Wp[16][256];   // [k2][row*2 + (k even/odd)]
    __shared__ float Xp[16][128];   // [k2][b*2 + (k even/odd)]

    const int tid = threadIdx.x;
    const int rbase = blockIdx.x * 128;   // 12 row tiles
    const int t = blockIdx.y;             // 1024 timesteps

    // reset scan-kernel launch state (graph-replay safe; stream-ordered before scan)
    if (blockIdx.x == 0 && t == 0) {
        if (tid < NBLK) g_flag[tid] = 0u;
        for (int i = tid; i < Bn * Hn; i += 256) g_h[0][i] = 0.f;
    }

    const int tx = tid & 15, ty = tid >> 4;
    const int r0 = ty * 8, b0 = tx * 4;

    ull acc[8][4];
#pragma unroll
    for (int i = 0; i < 8; i++)
#pragma unroll
        for (int j = 0; j < 4; j++) acc[i][j] = 0ull;

    for (int kc = 0; kc < In; kc += 32) {
#pragma unroll
        for (int i = tid; i < 1024; i += 256) {
            int r = i >> 3, kq = i & 7;
            float4 v = *(const float4*)&Wih[(size_t)(rbase + r) * In + kc + kq * 4];
            *(float2*)&Wp[kq * 2][r * 2]     = make_float2(v.x, v.y);
            *(float2*)&Wp[kq * 2 + 1][r * 2] = make_float2(v.z, v.w);
        }
#pragma unroll
        for (int i = tid; i < 512; i += 256) {
            int bb = i >> 3, kq = i & 7;
            float4 v = *(const float4*)&X[((size_t)t * Bn + bb) * In + kc + kq * 4];
            *(float2*)&Xp[kq * 2][bb * 2]     = make_float2(v.x, v.y);
            *(float2*)&Xp[kq * 2 + 1][bb * 2] = make_float2(v.z, v.w);
        }
        __syncthreads();

#pragma unroll
        for (int k2 = 0; k2 < 16; k2++) {
            ull w[8], x[4];
            ulonglong2 tmp;
            tmp = *(const ulonglong2*)&Wp[k2][(r0 + 0) * 2]; w[0] = tmp.x; w[1] = tmp.y;
            tmp = *(const ulonglong2*)&Wp[k2][(r0 + 2) * 2]; w[2] = tmp.x; w[3] = tmp.y;
            tmp = *(const ulonglong2*)&Wp[k2][(r0 + 4) * 2]; w[4] = tmp.x; w[5] = tmp.y;
            tmp = *(const ulonglong2*)&Wp[k2][(r0 + 6) * 2]; w[6] = tmp.x; w[7] = tmp.y;
            tmp = *(const ulonglong2*)&Xp[k2][(b0 + 0) * 2]; x[0] = tmp.x; x[1] = tmp.y;
            tmp = *(const ulonglong2*)&Xp[k2][(b0 + 2) * 2]; x[2] = tmp.x; x[3] = tmp.y;
#pragma unroll
            for (int i = 0; i < 8; i++)
#pragma unroll
                for (int j = 0; j < 4; j++)
                    fma2(acc[i][j], w[i], x[j]);
        }
        __syncthreads();
    }

#pragma unroll
    for (int i = 0; i < 8; i++) {
        float bias = bih[rbase + r0 + i];
        float4 o;
        o.x = hsum2(acc[i][0]) + bias;
        o.y = hsum2(acc[i][1]) + bias;
        o.z = hsum2(acc[i][2]) + bias;
        o.w = hsum2(acc[i][3]) + bias;
        *(float4*)&g_gi[((size_t)t * 1536 + rbase + r0 + i) * Bn + b0] = o;
    }
}

// =====================================================================
// Phase 2: persistent scan. 128 blocks x 256 threads. Warp kq owns the
// k-slice [kq*64, kq*64+64): stages ONLY its slice of h (LDG.cg -> STS,
// warp-local, so the dot needs just __syncwarp). Barrier = per-block
// release-store flag + one-warp vector acquire-poll (no L2 atomic
// serialization).
// =====================================================================
__global__ __launch_bounds__(256, 1) void gru_scan_kernel(
    const float* __restrict__ pad, const float* __restrict__ Whh,
    const float* __restrict__ bhh, float* __restrict__ out)
{
    extern __shared__ float sm[];
    float* W_s  = sm;                      // [12][512]  rows: g*4+jloc
    float* h_s  = W_s + 12 * Hn;           // [64][HPAD]
    float* p_s  = h_s + Bn * HPAD;         // [12][8][64] kq-partials
    float* hn_s = p_s + 12 * 8 * 64;       // [64][4]

    const int tid = threadIdx.x;
    const int blk = blockIdx.x;

    // gate-phase ids
    const int jj = tid >> 6;               // 0..3
    const int bg = tid & 63;
    const int j  = blk * JB + jj;

    // dot-phase ids
    const int kq = tid >> 5;               // warp id 0..7 = k-slice
    const int bp = tid & 31;               // lane

    // load this block's 12 W_hh rows once
    for (int i = tid; i < 12 * (Hn / 4); i += 256) {
        int row = i >> 7;                  // 0..11
        int kk  = i & 127;
        int g = row >> 2, jloc = row & 3;
        float4 v = *(const float4*)&Whh[(size_t)(g * Hn + blk * JB + jloc) * Hn + kk * 4];
        *(float4*)&W_s[row * Hn + kk * 4] = v;
    }
    const float bhr = bhh[j], bhz = bhh[Hn + j], bhn = bhh[2 * Hn + j];
    __syncthreads();

    const float* hp1 = &h_s[bp * HPAD + kq * 64];
    const float* hp2 = &h_s[(bp + 32) * HPAD + kq * 64];
    const float* wq  = &W_s[kq * 64];      // row r slice at wq + r*Hn
    const size_t states_off = (size_t)Bn * Tn * Hn;

    // staging geometry: lane bp handles idx = i*32+bp; row = idx>>4, c4 = idx&15
    const int st_c4 = (bp & 15) * 4;       // float col within slice
    const int st_r0 = bp >> 4;             // 0..1

    for (int t = 0; t < Tn; t++) {
        // gate-input loads first: DRAM latency hides under staging + FMAs
        const size_t gib = (size_t)t * 1536;
        float ir  = __ldg(&g_gi[(gib + j) * Bn + bg]);
        float iz  = __ldg(&g_gi[(gib + Hn + j) * Bn + bg]);
        float in_ = __ldg(&g_gi[(gib + 2 * Hn + j) * Bn + bg]);
        float p   = __ldg(&pad[t * Bn + bg]);

        // ---- stage own k-slice (64 rows x 64 cols), warp-local ----
        const float* hsrc = g_h[t & 1];
#pragma unroll
        for (int i = 0; i < 32; i++) {
            int row = i * 2 + st_r0;       // 0..63
            int col = kq * 64 + st_c4;
            float4 v = __ldcg((const float4*)&hsrc[row * Hn + col]);
            *(float4*)&h_s[row * HPAD + col] = v;
        }
        __syncwarp();

        // ---- dot phase: 12 rows x 2 batches over this warp's 64 k ----
        ull acc[12][2];
#pragma unroll
        for (int r = 0; r < 12; r++) { acc[r][0] = 0ull; acc[r][1] = 0ull; }

#pragma unroll
        for (int c = 0; c < 16; c++) {     // 4-k chunks
            ulonglong2 h1 = *(const ulonglong2*)&hp1[c * 4];
            ulonglong2 h2 = *(const ulonglong2*)&hp2[c * 4];
#pragma unroll
            for (int r = 0; r < 12; r++) {
                ulonglong2 w = *(const ulonglong2*)&wq[r * Hn + c * 4];
                fma2(acc[r][0], h1.x, w.x); fma2(acc[r][0], h1.y, w.y);
                fma2(acc[r][1], h2.x, w.x); fma2(acc[r][1], h2.y, w.y);
            }
        }
#pragma unroll
        for (int r = 0; r < 12; r++) {
            p_s[r * 512 + kq * 64 + bp]      = hsum2(acc[r][0]);
            p_s[r * 512 + kq * 64 + 32 + bp] = hsum2(acc[r][1]);
        }
        __syncthreads();

        // ---- reduce + gates: thread (jj, bg) ----
        float hr = bhr, hz = bhz, hv = bhn;
#pragma unroll
        for (int q = 0; q < 8; q++) {
            hr += p_s[(jj)     * 512 + q * 64 + bg];
            hz += p_s[(4 + jj) * 512 + q * 64 + bg];
            hv += p_s[(8 + jj) * 512 + q * 64 + bg];
        }
        float r = 1.f / (1.f + __expf(-(ir + hr)));
        float z = 1.f / (1.f + __expf(-(iz + hz)));
        float narg = in_ + r * hv;
        float n = 1.f - 2.f / (1.f + __expf(2.f * narg));   // tanh, saturation-safe
        float hold = h_s[bg * HPAD + j];
        float hc = (1.f - z) * n + z * hold;
        float hnew = p * hold + (1.f - p) * hc;

        hn_s[bg * JB + jj] = hnew;
        __syncthreads();

        // critical-path publish: next-step h slice
        if (tid < Bn) {
            float4 v = *(float4*)&hn_s[tid * JB];
            __stcg((float4*)&g_h[(t + 1) & 1][tid * Hn + blk * JB], v);
        }
        __syncthreads();                   // intra-block causality before release
        if (tid == 0) st_release_gpu(&g_flag[blk], (unsigned)(t + 1));

        // off-critical-path: output stores overlap other blocks' arrivals
        if (tid < Bn) {
            float4 v = *(float4*)&hn_s[tid * JB];
            size_t o = ((size_t)tid * Tn + t) * Hn + blk * JB;   // [B][T][H]
            *(float4*)&out[o] = v;
            *(float4*)&out[states_off + o] = v;                  // states == outputs
        }

        // wait: warp 0 polls all 128 flags (4 per lane), zero write contention
        if (tid < 32) {
            const unsigned target = (unsigned)(t + 1);
            const unsigned* fp = &g_flag[tid * 4];
            for (;;) {
                unsigned f0 = ld_acquire_gpu(fp + 0);
                unsigned f1 = ld_acquire_gpu(fp + 1);
                unsigned f2 = ld_acquire_gpu(fp + 2);
                unsigned f3 = ld_acquire_gpu(fp + 3);
                bool ok = (f0 >= target) & (f1 >= target) & (f2 >= target) & (f3 >= target);
                if (__all_sync(0xffffffffu, ok)) break;
            }
        }
        __syncthreads();
    }
}

// =====================================================================
extern "C" void kernel_launch(void* const* d_in, const int* in_sizes, int n_in,
                              void* d_out, int out_size) {
    const float* X   = (const float*)d_in[0];   // [T,B,I]
    const float* pad = (const float*)d_in[1];   // [T,B,1]
    const float* Wih = (const float*)d_in[2];   // [3H,I]
    const float* Whh = (const float*)d_in[3];   // [3H,H]
    const float* bih = (const float*)d_in[4];   // [3H]
    const float* bhh = (const float*)d_in[5];   // [3H]
    float* out = (float*)d_out;                 // [B,T,H] outputs ++ [B,T,H] states

    dim3 g1(12, Tn);
    gemm_ih_kernel<<<g1, 256>>>(X, Wih, bih);

    const int smem_bytes = (12 * Hn + Bn * HPAD + 12 * 8 * 64 + Bn * JB) * (int)sizeof(float);
    cudaFuncSetAttribute(gru_scan_kernel,
                         cudaFuncAttributeMaxDynamicSharedMemorySize, smem_bytes);
    gru_scan_kernel<<<NBLK, 256, smem_bytes>>>(pad, Whh, bhh, out);
}

// round 9
// speedup vs baseline: 1.1347x; 1.1347x over previous
#include <cuda_runtime.h>
#include <cstdint>
#include <cstddef>

// GRU: T=1024, B=64, I=512, H=512
#define Tn 1024
#define Bn 64
#define In 512
#define Hn 512
#define JB 4          // hidden units per block (scan)
#define HPAD 516      // padded h row: conflict-free 4-phase f4 LDS
#define NBLK 128      // scan blocks (<= #SMs, all co-resident)
#define FLAG_STRIDE 32 // one flag per 128B line

typedef unsigned long long ull;

// ---------------- device scratch (no allocations allowed) ----------------
__device__ float g_gi[(size_t)Tn * 1536 * Bn];   // [t][row(1536)][b]  ~402 MB
__device__ float g_h[2][Bn * Hn];                // ping-pong hidden state
__device__ unsigned g_flag[NBLK * FLAG_STRIDE];  // per-block epoch flags, line-padded

// ---------------- packed fp32x2 helpers (bit-exact 2x FFMA) ----------------
__device__ __forceinline__ void fma2(ull& d, ull a, ull b) {
    asm("fma.rn.f32x2 %0, %1, %2, %0;" : "+l"(d) : "l"(a), "l"(b));
}
__device__ __forceinline__ float hsum2(ull v) {
    float x, y;
    asm("mov.b64 {%0, %1}, %2;" : "=f"(x), "=f"(y) : "l"(v));
    return x + y;
}
__device__ __forceinline__ unsigned ld_acquire_gpu(const unsigned* p) {
    unsigned v;
    asm volatile("ld.acquire.gpu.global.u32 %0, [%1];" : "=r"(v) : "l"(p) : "memory");
    return v;
}
__device__ __forceinline__ void st_release_gpu(unsigned* p, unsigned v) {
    asm volatile("st.release.gpu.global.u32 [%0], %1;" :: "l"(p), "r"(v) : "memory");
}

// =====================================================================
// Phase 1: GI[t][row][b] = sum_k X[t][b][k] * Wih[row][k] + bih[row]
// =====================================================================
__global__ __launch_bounds__(256, 2) void gemm_ih_kernel(
    const float* __restrict__ X, const float* __restrict__ Wih,
    const float* __restrict__ bih)
{
    __shared__ float Wp[16][256];   // [k2][row*2 + (k even/odd)]
    __shared__ float Xp[16][128];   // [k2][b*2 + (k even/odd)]

    const int tid = threadIdx.x;
    const int rbase = blockIdx.x * 128;   // 12 row tiles
    const int t = blockIdx.y;             // 1024 timesteps

    // reset scan-kernel launch state (graph-replay safe; stream-ordered before scan)
    if (blockIdx.x == 0 && t == 0) {
        for (int i = tid; i < NBLK * FLAG_STRIDE; i += 256) g_flag[i] = 0u;
        for (int i = tid; i < Bn * Hn; i += 256) g_h[0][i] = 0.f;
    }

    const int tx = tid & 15, ty = tid >> 4;
    const int r0 = ty * 8, b0 = tx * 4;

    ull acc[8][4];
#pragma unroll
    for (int i = 0; i < 8; i++)
#pragma unroll
        for (int j = 0; j < 4; j++) acc[i][j] = 0ull;

    for (int kc = 0; kc < In; kc += 32) {
#pragma unroll
        for (int i = tid; i < 1024; i += 256) {
            int r = i >> 3, kq = i & 7;
            float4 v = *(const float4*)&Wih[(size_t)(rbase + r) * In + kc + kq * 4];
            *(float2*)&Wp[kq * 2][r * 2]     = make_float2(v.x, v.y);
            *(float2*)&Wp[kq * 2 + 1][r * 2] = make_float2(v.z, v.w);
        }
#pragma unroll
        for (int i = tid; i < 512; i += 256) {
            int bb = i >> 3, kq = i & 7;
            float4 v = *(const float4*)&X[((size_t)t * Bn + bb) * In + kc + kq * 4];
            *(float2*)&Xp[kq * 2][bb * 2]     = make_float2(v.x, v.y);
            *(float2*)&Xp[kq * 2 + 1][bb * 2] = make_float2(v.z, v.w);
        }
        __syncthreads();

#pragma unroll
        for (int k2 = 0; k2 < 16; k2++) {
            ull w[8], x[4];
            ulonglong2 tmp;
            tmp = *(const ulonglong2*)&Wp[k2][(r0 + 0) * 2]; w[0] = tmp.x; w[1] = tmp.y;
            tmp = *(const ulonglong2*)&Wp[k2][(r0 + 2) * 2]; w[2] = tmp.x; w[3] = tmp.y;
            tmp = *(const ulonglong2*)&Wp[k2][(r0 + 4) * 2]; w[4] = tmp.x; w[5] = tmp.y;
            tmp = *(const ulonglong2*)&Wp[k2][(r0 + 6) * 2]; w[6] = tmp.x; w[7] = tmp.y;
            tmp = *(const ulonglong2*)&Xp[k2][(b0 + 0) * 2]; x[0] = tmp.x; x[1] = tmp.y;
            tmp = *(const ulonglong2*)&Xp[k2][(b0 + 2) * 2]; x[2] = tmp.x; x[3] = tmp.y;
#pragma unroll
            for (int i = 0; i < 8; i++)
#pragma unroll
                for (int j = 0; j < 4; j++)
                    fma2(acc[i][j], w[i], x[j]);
        }
        __syncthreads();
    }

#pragma unroll
    for (int i = 0; i < 8; i++) {
        float bias = bih[rbase + r0 + i];
        float4 o;
        o.x = hsum2(acc[i][0]) + bias;
        o.y = hsum2(acc[i][1]) + bias;
        o.z = hsum2(acc[i][2]) + bias;
        o.w = hsum2(acc[i][3]) + bias;
        *(float4*)&g_gi[((size_t)t * 1536 + rbase + r0 + i) * Bn + b0] = o;
    }
}

// =====================================================================
// Phase 2: persistent scan — EXACT R3 compute structure (best passing,
// 11218us). ONLY the barrier differs from R3: release-store to a
// line-padded per-block flag (no atomic drain), every block's warp 0
// polls all 128 flags directly (R6-proven pattern, now spread over 128
// L2 lines instead of 4).
// =====================================================================
__global__ __launch_bounds__(256, 1) void gru_scan_kernel(
    const float* __restrict__ pad, const float* __restrict__ Whh,
    const float* __restrict__ bhh, float* __restrict__ out)
{
    extern __shared__ float sm[];
    float* W_s  = sm;                      // [12][512]  rows: g*4+jloc
    float* h_s  = W_s + 12 * Hn;           // [64][HPAD]
    float* p_s  = h_s + Bn * HPAD;         // [12][8][64] kq-partials
    float* hn_s = p_s + 12 * 8 * 64;       // [64][4]

    const int tid = threadIdx.x;
    const int blk = blockIdx.x;

    // gate-phase ids
    const int jj = tid >> 6;               // 0..3
    const int bg = tid & 63;
    const int j  = blk * JB + jj;

    // dot-phase ids
    const int kq = tid >> 5;               // warp id 0..7 = k-slice
    const int bp = tid & 31;

    // load this block's 12 W_hh rows once
    for (int i = tid; i < 12 * (Hn / 4); i += 256) {
        int row = i >> 7;                  // 0..11
        int kk  = i & 127;
        int g = row >> 2, jloc = row & 3;
        float4 v = *(const float4*)&Whh[(size_t)(g * Hn + blk * JB + jloc) * Hn + kk * 4];
        *(float4*)&W_s[row * Hn + kk * 4] = v;
    }
    const float bhr = bhh[j], bhz = bhh[Hn + j], bhn = bhh[2 * Hn + j];
    __syncthreads();

    const float* hp1 = &h_s[bp * HPAD + kq * 64];
    const float* hp2 = &h_s[(bp + 32) * HPAD + kq * 64];
    const float* wq  = &W_s[kq * 64];      // row r slice at wq + r*Hn
    const size_t states_off = (size_t)Bn * Tn * Hn;

    for (int t = 0; t < Tn; t++) {
        // gate-input loads first: DRAM latency hides under staging + FMAs
        const size_t gib = (size_t)t * 1536;
        float ir  = __ldg(&g_gi[(gib + j) * Bn + bg]);
        float iz  = __ldg(&g_gi[(gib + Hn + j) * Bn + bg]);
        float in_ = __ldg(&g_gi[(gib + 2 * Hn + j) * Bn + bg]);
        float p   = __ldg(&pad[t * Bn + bg]);

        // stage h[t] from L2 (bypass L1: remote SMs wrote it) — block-wide
        const float* hsrc = g_h[t & 1];
        for (int i = tid; i < Bn * (Hn / 4); i += 256) {
            int bb = i >> 7, kk = i & 127;
            float4 v = __ldcg((const float4*)&hsrc[bb * Hn + kk * 4]);
            *(float4*)&h_s[bb * HPAD + kk * 4] = v;
        }
        __syncthreads();

        // ---- dot phase: 12 rows x 2 batches over this warp's 64 k ----
        ull acc[12][2];
#pragma unroll
        for (int r = 0; r < 12; r++) { acc[r][0] = 0ull; acc[r][1] = 0ull; }

#pragma unroll
        for (int c = 0; c < 16; c++) {     // 4-k chunks
            ulonglong2 h1 = *(const ulonglong2*)&hp1[c * 4];
            ulonglong2 h2 = *(const ulonglong2*)&hp2[c * 4];
#pragma unroll
            for (int r = 0; r < 12; r++) {
                ulonglong2 w = *(const ulonglong2*)&wq[r * Hn + c * 4];
                fma2(acc[r][0], h1.x, w.x); fma2(acc[r][0], h1.y, w.y);
                fma2(acc[r][1], h2.x, w.x); fma2(acc[r][1], h2.y, w.y);
            }
        }
#pragma unroll
        for (int r = 0; r < 12; r++) {
            p_s[r * 512 + kq * 64 + bp]      = hsum2(acc[r][0]);
            p_s[r * 512 + kq * 64 + 32 + bp] = hsum2(acc[r][1]);
        }
        __syncthreads();

        // ---- reduce + gates: thread (jj, bg) ----
        float hr = bhr, hz = bhz, hv = bhn;
#pragma unroll
        for (int q = 0; q < 8; q++) {
            hr += p_s[(jj)     * 512 + q * 64 + bg];
            hz += p_s[(4 + jj) * 512 + q * 64 + bg];
            hv += p_s[(8 + jj) * 512 + q * 64 + bg];
        }
        float r = 1.f / (1.f + __expf(-(ir + hr)));
        float z = 1.f / (1.f + __expf(-(iz + hz)));
        float narg = in_ + r * hv;
        float n = 1.f - 2.f / (1.f + __expf(2.f * narg));   // tanh, saturation-safe
        float hold = h_s[bg * HPAD + j];
        float hc = (1.f - z) * n + z * hold;
        float hnew = p * hold + (1.f - p) * hc;

        hn_s[bg * JB + jj] = hnew;
        __syncthreads();

        // critical-path publish: next-step h slice
        if (tid < Bn) {
            float4 v = *(float4*)&hn_s[tid * JB];
            __stcg((float4*)&g_h[(t + 1) & 1][tid * Hn + blk * JB], v);
        }
        __syncthreads();                   // intra-block causality before release
        if (tid == 0) st_release_gpu(&g_flag[blk * FLAG_STRIDE], (unsigned)(t + 1));

        // off-critical-path: output stores overlap the barrier window
        if (tid < Bn) {
            float4 v = *(float4*)&hn_s[tid * JB];
            size_t o = ((size_t)tid * Tn + t) * Hn + blk * JB;   // [B][T][H]
            *(float4*)&out[o] = v;
            *(float4*)&out[states_off + o] = v;                  // states == outputs
        }

        // wait: every block's warp 0 polls all 128 flags, 4 per lane,
        // each flag on its OWN 128B line (parallel LTS slices)
        if (tid < 32) {
            const unsigned target = (unsigned)(t + 1);
            for (;;) {
                bool ok = (ld_acquire_gpu(&g_flag[(tid)      * FLAG_STRIDE]) >= target)
                        & (ld_acquire_gpu(&g_flag[(tid + 32) * FLAG_STRIDE]) >= target)
                        & (ld_acquire_gpu(&g_flag[(tid + 64) * FLAG_STRIDE]) >= target)
                        & (ld_acquire_gpu(&g_flag[(tid + 96) * FLAG_STRIDE]) >= target);
                if (__all_sync(0xffffffffu, ok)) break;
            }
        }
        __syncthreads();
    }
}

// =====================================================================
extern "C" void kernel_launch(void* const* d_in, const int* in_sizes, int n_in,
                              void* d_out, int out_size) {
    const float* X   = (const float*)d_in[0];   // [T,B,I]
    const float* pad = (const float*)d_in[1];   // [T,B,1]
    const float* Wih = (const float*)d_in[2];   // [3H,I]
    const float* Whh = (const float*)d_in[3];   // [3H,H]
    const float* bih = (const float*)d_in[4];   // [3H]
    const float* bhh = (const float*)d_in[5];   // [3H]
    float* out = (float*)d_out;                 // [B,T,H] outputs ++ [B,T,H] states

    dim3 g1(12, Tn);
    gemm_ih_kernel<<<g1, 256>>>(X, Wih, bih);

    const int smem_bytes = (12 * Hn + Bn * HPAD + 12 * 8 * 64 + Bn * JB) * (int)sizeof(float);
    cudaFuncSetAttribute(gru_scan_kernel,
                         cudaFuncAttributeMaxDynamicSharedMemorySize, smem_bytes);
    gru_scan_kernel<<<NBLK, 256, smem_bytes>>>(pad, Whh, bhh, out);
}

// round 10
// speedup vs baseline: 1.4777x; 1.3023x over previous
#include <cuda_runtime.h>
#include <cstdint>
#include <cstddef>

// GRU: T=1024, B=64, I=512, H=512
#define Tn 1024
#define Bn 64
#define In 512
#define Hn 512
#define NBLK 128       // scan blocks (<= #SMs, all co-resident)
#define GRP 4          // independent batch groups
#define BPG 32         // blocks per group
#define BATG 16        // batches per group
#define JPB 16         // hidden units per block -> 48 W rows
#define HPAD 516       // padded h row
#define FLAG_STRIDE 32 // one flag per 128B line

typedef unsigned long long ull;

// ---------------- device scratch (no allocations allowed) ----------------
__device__ float g_gi[(size_t)Tn * 1536 * Bn];   // [t][row(1536)][b]  ~402 MB
__device__ float g_h[2][Bn * Hn];                // ping-pong hidden state [b][j]
__device__ unsigned g_flag[NBLK * FLAG_STRIDE];  // per-block epoch flags, line-padded

// ---------------- packed fp32x2 helpers (bit-exact 2x FFMA) ----------------
__device__ __forceinline__ void fma2(ull& d, ull a, ull b) {
    asm("fma.rn.f32x2 %0, %1, %2, %0;" : "+l"(d) : "l"(a), "l"(b));
}
__device__ __forceinline__ float hsum2(ull v) {
    float x, y;
    asm("mov.b64 {%0, %1}, %2;" : "=f"(x), "=f"(y) : "l"(v));
    return x + y;
}
__device__ __forceinline__ unsigned ld_acquire_gpu(const unsigned* p) {
    unsigned v;
    asm volatile("ld.acquire.gpu.global.u32 %0, [%1];" : "=r"(v) : "l"(p) : "memory");
    return v;
}
__device__ __forceinline__ void st_release_gpu(unsigned* p, unsigned v) {
    asm volatile("st.release.gpu.global.u32 [%0], %1;" :: "l"(p), "r"(v) : "memory");
}

// =====================================================================
// Phase 1: GI[t][row][b] = sum_k X[t][b][k] * Wih[row][k] + bih[row]
// =====================================================================
__global__ __launch_bounds__(256, 2) void gemm_ih_kernel(
    const float* __restrict__ X, const float* __restrict__ Wih,
    const float* __restrict__ bih)
{
    __shared__ float Wp[16][256];
    __shared__ float Xp[16][128];

    const int tid = threadIdx.x;
    const int rbase = blockIdx.x * 128;
    const int t = blockIdx.y;

    if (blockIdx.x == 0 && t == 0) {
        for (int i = tid; i < NBLK * FLAG_STRIDE; i += 256) g_flag[i] = 0u;
        for (int i = tid; i < Bn * Hn; i += 256) g_h[0][i] = 0.f;
    }

    const int tx = tid & 15, ty = tid >> 4;
    const int r0 = ty * 8, b0 = tx * 4;

    ull acc[8][4];
#pragma unroll
    for (int i = 0; i < 8; i++)
#pragma unroll
        for (int j = 0; j < 4; j++) acc[i][j] = 0ull;

    for (int kc = 0; kc < In; kc += 32) {
#pragma unroll
        for (int i = tid; i < 1024; i += 256) {
            int r = i >> 3, kq = i & 7;
            float4 v = *(const float4*)&Wih[(size_t)(rbase + r) * In + kc + kq * 4];
            *(float2*)&Wp[kq * 2][r * 2]     = make_float2(v.x, v.y);
            *(float2*)&Wp[kq * 2 + 1][r * 2] = make_float2(v.z, v.w);
        }
#pragma unroll
        for (int i = tid; i < 512; i += 256) {
            int bb = i >> 3, kq = i & 7;
            float4 v = *(const float4*)&X[((size_t)t * Bn + bb) * In + kc + kq * 4];
            *(float2*)&Xp[kq * 2][bb * 2]     = make_float2(v.x, v.y);
            *(float2*)&Xp[kq * 2 + 1][bb * 2] = make_float2(v.z, v.w);
        }
        __syncthreads();

#pragma unroll
        for (int k2 = 0; k2 < 16; k2++) {
            ull w[8], x[4];
            ulonglong2 tmp;
            tmp = *(const ulonglong2*)&Wp[k2][(r0 + 0) * 2]; w[0] = tmp.x; w[1] = tmp.y;
            tmp = *(const ulonglong2*)&Wp[k2][(r0 + 2) * 2]; w[2] = tmp.x; w[3] = tmp.y;
            tmp = *(const ulonglong2*)&Wp[k2][(r0 + 4) * 2]; w[4] = tmp.x; w[5] = tmp.y;
            tmp = *(const ulonglong2*)&Wp[k2][(r0 + 6) * 2]; w[6] = tmp.x; w[7] = tmp.y;
            tmp = *(const ulonglong2*)&Xp[k2][(b0 + 0) * 2]; x[0] = tmp.x; x[1] = tmp.y;
            tmp = *(const ulonglong2*)&Xp[k2][(b0 + 2) * 2]; x[2] = tmp.x; x[3] = tmp.y;
#pragma unroll
            for (int i = 0; i < 8; i++)
#pragma unroll
                for (int j = 0; j < 4; j++)
                    fma2(acc[i][j], w[i], x[j]);
        }
        __syncthreads();
    }

#pragma unroll
    for (int i = 0; i < 8; i++) {
        float bias = bih[rbase + r0 + i];
        float4 o;
        o.x = hsum2(acc[i][0]) + bias;
        o.y = hsum2(acc[i][1]) + bias;
        o.z = hsum2(acc[i][2]) + bias;
        o.w = hsum2(acc[i][3]) + bias;
        *(float4*)&g_gi[((size_t)t * 1536 + rbase + r0 + i) * Bn + b0] = o;
    }
}

// =====================================================================
// Phase 2: persistent scan, (batch-group x j-slice) partitioned.
// Group g (4 groups x 32 blocks) owns batches [16g,16g+16) — groups are
// fully independent chains (GRU recurrence is batch-independent).
// Block bi in group owns j in [16bi,16bi+16): its 48 W_hh rows live in
// smem forever. Per step: stage 32KB group-h, kq-slice dot (fma2),
// group-internal reduce/gates, publish, 32-block flag barrier.
// =====================================================================
__global__ __launch_bounds__(256, 1) void gru_scan_kernel(
    const float* __restrict__ pad, const float* __restrict__ Whh,
    const float* __restrict__ bhh, float* __restrict__ out)
{
    extern __shared__ float sm[];
    float* W_s  = sm;                        // [48][512]  rows: gate*16 + j_loc
    float* h_s  = W_s + 48 * Hn;             // [16][HPAD]
    float* p_s  = h_s + BATG * HPAD;         // [48][8][16] kq-partials
    float* hn_s = p_s + 48 * 8 * BATG;       // [16][16]  [batch][j_loc]

    const int tid = threadIdx.x;
    const int blk = blockIdx.x;
    const int grp = blk >> 5;                // group 0..3
    const int bi  = blk & 31;                // block in group
    const int gb  = grp * BATG;              // batch base
    const int jb  = bi * JPB;                // j base

    // dot-phase ids
    const int kq = tid >> 5;                 // warp 0..7 = 64-k slice
    const int bp = tid & 31;
    const int bq_d = bp & 15;                // batch within group (dot)
    const int rh   = bp >> 4;                // row half: rows [rh*24, rh*24+24)

    // gate-phase ids
    const int j_loc = tid >> 4;              // 0..15
    const int bq_g  = tid & 15;              // batch within group (gates)

    // load this block's 48 W_hh rows once (row rr = gate*16 + j_loc)
    for (int i = tid; i < 48 * (Hn / 4); i += 256) {
        int rr = i >> 7;                     // 0..47
        int kk = i & 127;
        int gate = rr >> 4, jl = rr & 15;
        float4 v = *(const float4*)&Whh[(size_t)(gate * Hn + jb + jl) * Hn + kk * 4];
        *(float4*)&W_s[rr * Hn + kk * 4] = v;
    }
    const float bhr = bhh[jb + j_loc];
    const float bhz = bhh[Hn + jb + j_loc];
    const float bhn = bhh[2 * Hn + jb + j_loc];
    __syncthreads();

    const float* hb = &h_s[bq_d * HPAD + kq * 64];
    const float* wq = &W_s[(rh * 24) * Hn + kq * 64];   // 24 rows at stride Hn
    const size_t states_off = (size_t)Bn * Tn * Hn;

    for (int t = 0; t < Tn; t++) {
        // gate-input loads first: DRAM latency hides under staging + FMAs
        const size_t gib = (size_t)t * 1536;
        const int jg = jb + j_loc;
        const int bgl = gb + bq_g;
        float ir  = __ldg(&g_gi[(gib + jg) * Bn + bgl]);
        float iz  = __ldg(&g_gi[(gib + Hn + jg) * Bn + bgl]);
        float in_ = __ldg(&g_gi[(gib + 2 * Hn + jg) * Bn + bgl]);
        float p   = __ldg(&pad[t * Bn + bgl]);

        // stage group's h[t] (16 batches x 512) from L2 (.cg: remote writes)
        const float* hsrc = g_h[t & 1];
        for (int i = tid; i < BATG * (Hn / 4); i += 256) {
            int bb = i >> 7, kk = i & 127;
            float4 v = __ldcg((const float4*)&hsrc[(gb + bb) * Hn + kk * 4]);
            *(float4*)&h_s[bb * HPAD + kk * 4] = v;
        }
        __syncthreads();

        // ---- dot: 24 rows x 1 batch over this warp's 64 k ----
        ull acc[24];
#pragma unroll
        for (int r = 0; r < 24; r++) acc[r] = 0ull;

#pragma unroll
        for (int c = 0; c < 16; c++) {       // 4-k chunks
            ulonglong2 hh = *(const ulonglong2*)&hb[c * 4];
#pragma unroll
            for (int r = 0; r < 24; r++) {
                ulonglong2 w = *(const ulonglong2*)&wq[r * Hn + c * 4];
                fma2(acc[r], hh.x, w.x);
                fma2(acc[r], hh.y, w.y);
            }
        }
#pragma unroll
        for (int r = 0; r < 24; r++)
            p_s[(rh * 24 + r) * 128 + kq * 16 + bq_d] = hsum2(acc[r]);
        __syncthreads();

        // ---- reduce + gates: thread (j_loc, bq_g) ----
        float hr = bhr, hz = bhz, hv = bhn;
#pragma unroll
        for (int q = 0; q < 8; q++) {
            hr += p_s[(j_loc)      * 128 + q * 16 + bq_g];
            hz += p_s[(16 + j_loc) * 128 + q * 16 + bq_g];
            hv += p_s[(32 + j_loc) * 128 + q * 16 + bq_g];
        }
        float r = 1.f / (1.f + __expf(-(ir + hr)));
        float z = 1.f / (1.f + __expf(-(iz + hz)));
        float narg = in_ + r * hv;
        float n = 1.f - 2.f / (1.f + __expf(2.f * narg));   // tanh, saturation-safe
        float hold = h_s[bq_g * HPAD + jg];
        float hc = (1.f - z) * n + z * hold;
        float hnew = p * hold + (1.f - p) * hc;

        hn_s[bq_g * JPB + j_loc] = hnew;
        __syncthreads();

        // critical-path publish: this block's 16x16 h tile
        if (tid < 64) {
            int bb = tid >> 2, jq = tid & 3;
            float4 v = *(float4*)&hn_s[bb * JPB + jq * 4];
            __stcg((float4*)&g_h[(t + 1) & 1][(gb + bb) * Hn + jb + jq * 4], v);
        }
        __syncthreads();                     // intra-block causality before release
        if (tid == 0) st_release_gpu(&g_flag[blk * FLAG_STRIDE], (unsigned)(t + 1));

        // off-critical-path: outputs overlap the (group-internal) barrier
        if (tid < 64) {
            int bb = tid >> 2, jq = tid & 3;
            float4 v = *(float4*)&hn_s[bb * JPB + jq * 4];
            size_t o = ((size_t)(gb + bb) * Tn + t) * Hn + jb + jq * 4;  // [B][T][H]
            *(float4*)&out[o] = v;
            *(float4*)&out[states_off + o] = v;                          // states == outputs
        }

        // wait: warp 0 polls ONLY its group's 32 flags, 1 per lane, 1 line each
        if (tid < 32) {
            const unsigned target = (unsigned)(t + 1);
            const unsigned* fp = &g_flag[(grp * BPG + tid) * FLAG_STRIDE];
            while (!__all_sync(0xffffffffu, ld_acquire_gpu(fp) >= target)) { }
        }
        __syncthreads();
    }
}

// =====================================================================
extern "C" void kernel_launch(void* const* d_in, const int* in_sizes, int n_in,
                              void* d_out, int out_size) {
    const float* X   = (const float*)d_in[0];   // [T,B,I]
    const float* pad = (const float*)d_in[1];   // [T,B,1]
    const float* Wih = (const float*)d_in[2];   // [3H,I]
    const float* Whh = (const float*)d_in[3];   // [3H,H]
    const float* bih = (const float*)d_in[4];   // [3H]
    const float* bhh = (const float*)d_in[5];   // [3H]
    float* out = (float*)d_out;                 // [B,T,H] outputs ++ [B,T,H] states

    dim3 g1(12, Tn);
    gemm_ih_kernel<<<g1, 256>>>(X, Wih, bih);

    const int smem_bytes = (48 * Hn + BATG * HPAD + 48 * 8 * BATG + BATG * JPB)
                           * (int)sizeof(float);   // ~157 KB
    cudaFuncSetAttribute(gru_scan_kernel,
                         cudaFuncAttributeMaxDynamicSharedMemorySize, smem_bytes);
    gru_scan_kernel<<<NBLK, 256, smem_bytes>>>(pad, Whh, bhh, out);
}